// round 6
// baseline (speedup 1.0000x reference)
#include <cuda_runtime.h>
#include <cuda_bf16.h>
#include <cstdint>

#define NROWS 16384
#define DIM   256
#define NT    128
#define NTILES 8256                // NT*(NT+1)/2
#define NCTA  148
#define LDSB  272                  // bytes per smem row (256 + 16 pad)
#define KS    (5.0f / 256.0f)      // kappa folded with 16x16 quant scaling
#define TILE_SM_BYTES (128 * LDSB)             // 34816
#define SMEM_BYTES (3 * TILE_SM_BYTES)         // A + 2x B = 104448

__device__ uint8_t g_xq[NROWS * DIM];   // normalized rows, e4m3, scaled by 16
__device__ float   g_density[NROWS];

// ---------------- Phase 1: L2-normalize rows -> e4m3 (x16); zero g_density ----------------
static __device__ __forceinline__ uint16_t pack_e4m3x2(float lo, float hi) {
    uint16_t r;
    asm("cvt.rn.satfinite.e4m3x2.f32 %0, %1, %2;" : "=h"(r) : "f"(hi), "f"(lo));
    return r;
}

__global__ void normalize_kernel(const float* __restrict__ x) {
    int gwarp = (blockIdx.x * blockDim.x + threadIdx.x) >> 5;
    int lane  = threadIdx.x & 31;
    if (gwarp >= NROWS) return;
    const float4* p = reinterpret_cast<const float4*>(x + (size_t)gwarp * DIM);
    float4 v0 = p[lane * 2 + 0];
    float4 v1 = p[lane * 2 + 1];
    float ss = v0.x*v0.x + v0.y*v0.y + v0.z*v0.z + v0.w*v0.w
             + v1.x*v1.x + v1.y*v1.y + v1.z*v1.z + v1.w*v1.w;
    #pragma unroll
    for (int o = 16; o; o >>= 1) ss += __shfl_xor_sync(0xffffffffu, ss, o);
    float inv = 16.0f / fmaxf(sqrtf(ss), 1e-12f);

    uint16_t b01 = pack_e4m3x2(v0.x * inv, v0.y * inv);
    uint16_t b23 = pack_e4m3x2(v0.z * inv, v0.w * inv);
    uint16_t b45 = pack_e4m3x2(v1.x * inv, v1.y * inv);
    uint16_t b67 = pack_e4m3x2(v1.z * inv, v1.w * inv);
    uint2 out;
    out.x = (uint32_t)b01 | ((uint32_t)b23 << 16);
    out.y = (uint32_t)b45 | ((uint32_t)b67 << 16);
    reinterpret_cast<uint2*>(g_xq)[gwarp * (DIM / 8) + lane] = out;
    if (lane == 0) g_density[gwarp] = 0.0f;
}

// ---------------- helpers ----------------
static __device__ __forceinline__ void ldsm_x4(uint32_t* r, uint32_t addr) {
    asm volatile("ldmatrix.sync.aligned.m8n8.x4.shared.b16 {%0,%1,%2,%3}, [%4];\n"
                 : "=r"(r[0]), "=r"(r[1]), "=r"(r[2]), "=r"(r[3]) : "r"(addr));
}
static __device__ __forceinline__ void mma_fp8(float* c, const uint32_t* a, const uint32_t* b) {
    asm volatile("mma.sync.aligned.m16n8k32.row.col.f32.e4m3.e4m3.f32 "
                 "{%0,%1,%2,%3}, {%4,%5,%6,%7}, {%8,%9}, {%0,%1,%2,%3};\n"
                 : "+f"(c[0]), "+f"(c[1]), "+f"(c[2]), "+f"(c[3])
                 : "r"(a[0]), "r"(a[1]), "r"(a[2]), "r"(a[3]),
                   "r"(b[0]), "r"(b[1]));
}
#define CP_ASYNC16(dst, src) \
    asm volatile("cp.async.cg.shared.global [%0], [%1], 16;" :: "r"(dst), "l"(src) : "memory")
#define CP_COMMIT()  asm volatile("cp.async.commit_group;" ::: "memory")
#define CP_WAIT0()   asm volatile("cp.async.wait_group 0;" :: : "memory")

// load a 128x256B fp8 tile (2048 x 16B, 8 per thread)
static __device__ __forceinline__ void load_tile(uint32_t dst_base, int grow0, int tid) {
    #pragma unroll
    for (int i = 0; i < 8; ++i) {
        int id = i * 256 + tid;
        int r = id >> 4, u = id & 15;
        uint32_t dst = dst_base + (uint32_t)(r * LDSB + u * 16);
        const char* src = (const char*)g_xq + (size_t)(grow0 + r) * DIM + u * 16;
        CP_ASYNC16(dst, src);
    }
}

// pair-ordered global tile index -> (ti, tj), ti <= tj
static __device__ __forceinline__ void tile_of(int q, int& ti, int& tj) {
    int p = q / 129, r = q - p * 129;
    int seg1 = NT - p;
    if (r < seg1) { ti = p;          tj = p + r; }
    else          { ti = NT - 1 - p; tj = NT - 1 - p + (r - seg1); }
}

// exp-epilogue of one nf-chunk of the previous tile's accumulators
static __device__ __forceinline__ void epi_chunk(int ks, float cfrB[2][8][4],
                                                 float rowacc[2][2], float colaccP[8][2]) {
    float c0 = 0.f, c1 = 0.f;
    #pragma unroll
    for (int mf = 0; mf < 2; ++mf) {
        float e0 = __expf(KS * cfrB[mf][ks][0]);
        float e1 = __expf(KS * cfrB[mf][ks][1]);
        float e2 = __expf(KS * cfrB[mf][ks][2]);
        float e3 = __expf(KS * cfrB[mf][ks][3]);
        rowacc[mf][0] += e0 + e1;
        rowacc[mf][1] += e2 + e3;
        c0 += e0 + e2;
        c1 += e1 + e3;
    }
    colaccP[ks][0] = c0;
    colaccP[ks][1] = c1;
}

template <bool EPI>
static __device__ __forceinline__ void tile_mainloop(
    uint32_t Ab, uint32_t Bb, int a_rb, int b_rb,
    float cfrA[2][8][4], float cfrB[2][8][4],
    float rowacc[2][2], float colaccP[8][2])
{
    #pragma unroll
    for (int ks = 0; ks < 8; ++ks) {
        int k0 = ks * 32;
        uint32_t a[2][4];
        #pragma unroll
        for (int mf = 0; mf < 2; ++mf)
            ldsm_x4(a[mf], Ab + (uint32_t)(mf * 16 * LDSB + a_rb + k0));
        uint32_t bfr[8][2];
        #pragma unroll
        for (int pp = 0; pp < 4; ++pp) {
            uint32_t t[4];
            ldsm_x4(t, Bb + (uint32_t)(pp * 16 * LDSB + b_rb + k0));
            bfr[2*pp][0]   = t[0]; bfr[2*pp][1]   = t[1];
            bfr[2*pp+1][0] = t[2]; bfr[2*pp+1][1] = t[3];
        }
        #pragma unroll
        for (int mf = 0; mf < 2; ++mf)
            #pragma unroll
            for (int nf = 0; nf < 8; ++nf)
                mma_fp8(cfrA[mf][nf], a[mf], bfr[nf]);
        if (EPI)
            epi_chunk(ks, cfrB, rowacc, colaccP);   // overlaps MMA stalls: MUFU/FMA pipes
    }
}

static __device__ __forceinline__ void flush_cols(float colaccP[8][2], int tj,
                                                  int warp_n, int lane) {
    #pragma unroll
    for (int nf = 0; nf < 8; ++nf)
        #pragma unroll
        for (int hh = 0; hh < 2; ++hh) {
            float s = colaccP[nf][hh];
            s += __shfl_xor_sync(0xffffffffu, s, 4);
            s += __shfl_xor_sync(0xffffffffu, s, 8);
            s += __shfl_xor_sync(0xffffffffu, s, 16);
            if (lane < 4)
                atomicAdd(&g_density[tj * 128 + warp_n * 64 + nf * 8 + 2 * lane + hh], s);
        }
}

static __device__ __forceinline__ void flush_rows(float rowacc[2][2], int ti,
                                                  int warp_m, int lane) {
    #pragma unroll
    for (int mf = 0; mf < 2; ++mf)
        #pragma unroll
        for (int rp = 0; rp < 2; ++rp) {
            float s = rowacc[mf][rp];
            s += __shfl_xor_sync(0xffffffffu, s, 1);
            s += __shfl_xor_sync(0xffffffffu, s, 2);
            if ((lane & 3) == 0)
                atomicAdd(&g_density[ti * 128 + warp_m * 32 + mf * 16 + rp * 8 + (lane >> 2)], s);
            rowacc[mf][rp] = 0.f;
        }
}

// ---------------- Phase 2: persistent FP8 symmetric GEMM, pipelined epilogue ----------------
__global__ void __launch_bounds__(256, 1) kde_sym_kernel() {
    extern __shared__ uint8_t sm[];
    uint32_t A_sm = (uint32_t)__cvta_generic_to_shared(sm);
    uint32_t B_sm = A_sm + TILE_SM_BYTES;

    int tid  = threadIdx.x;
    int lane = tid & 31;
    int wid  = tid >> 5;
    int warp_m = wid & 3;
    int warp_n = wid >> 2;

    int qbeg = (int)(((long long)blockIdx.x * NTILES) / NCTA);
    int qend = (int)(((long long)(blockIdx.x + 1) * NTILES) / NCTA);

    int a_rb = (lane & 15) * LDSB + ((lane >> 4) * 16);
    int b_rb = ((lane & 7) + ((lane >> 4) << 3)) * LDSB + (((lane >> 3) & 1) * 16);
    uint32_t Ab = A_sm + (uint32_t)(warp_m * 32 * LDSB);

    int ti, tj;
    tile_of(qbeg, ti, tj);
    int cur_ti = ti;

    load_tile(A_sm, ti * 128, tid);
    load_tile(B_sm, tj * 128, tid);
    CP_COMMIT();
    CP_WAIT0();
    __syncthreads();

    float rowacc[2][2] = {{0.f,0.f},{0.f,0.f}};
    float cfrA[2][8][4], cfrB[2][8][4], colaccP[8][2];
    int cur = 0;
    int prev_tj = 0;
    bool prev_diag = false, have_prev = false;

    for (int q = qbeg; q < qend; ++q) {
        tile_of(q, ti, tj);
        if (q > qbeg) { CP_WAIT0(); __syncthreads(); }   // B(q) resident in buf cur

        int flush_ti = -1;
        if (ti != cur_ti) {                               // rare: <=1 per CTA
            load_tile(A_sm, ti * 128, tid);
            CP_COMMIT(); CP_WAIT0(); __syncthreads();
            flush_ti = cur_ti;
            cur_ti = ti;
        }

        if (q + 1 < qend) {                               // prefetch next B
            int nti, ntj;
            tile_of(q + 1, nti, ntj);
            load_tile(B_sm + (cur ^ 1) * TILE_SM_BYTES, ntj * 128, tid);
            CP_COMMIT();
        }

        #pragma unroll
        for (int mf = 0; mf < 2; ++mf)
            #pragma unroll
            for (int nf = 0; nf < 8; ++nf)
                #pragma unroll
                for (int e = 0; e < 4; ++e) cfrA[mf][nf][e] = 0.f;

        uint32_t Bb = B_sm + (uint32_t)(cur * TILE_SM_BYTES + warp_n * 64 * LDSB);
        if (have_prev)
            tile_mainloop<true >(Ab, Bb, a_rb, b_rb, cfrA, cfrB, rowacc, colaccP);
        else
            tile_mainloop<false>(Ab, Bb, a_rb, b_rb, cfrA, cfrB, rowacc, colaccP);

        if (have_prev && !prev_diag) flush_cols(colaccP, prev_tj, warp_n, lane);
        if (flush_ti >= 0) flush_rows(rowacc, flush_ti, warp_m, lane);

        #pragma unroll
        for (int mf = 0; mf < 2; ++mf)
            #pragma unroll
            for (int nf = 0; nf < 8; ++nf)
                #pragma unroll
                for (int e = 0; e < 4; ++e) cfrB[mf][nf][e] = cfrA[mf][nf][e];

        prev_tj = tj;
        prev_diag = (ti == tj);
        have_prev = true;
        cur ^= 1;
    }

    // drain last tile's epilogue
    #pragma unroll
    for (int ks = 0; ks < 8; ++ks)
        epi_chunk(ks, cfrB, rowacc, colaccP);
    if (!prev_diag) flush_cols(colaccP, prev_tj, warp_n, lane);
    flush_rows(rowacc, cur_ti, warp_m, lane);
}

// ---------------- Phase 3: entropy = -mean(log(density + 1e-9)) ----------------
__global__ void entropy_kernel(float* __restrict__ out) {
    __shared__ float red[1024];
    int t = threadIdx.x;
    float s = 0.f;
    for (int i = t; i < NROWS; i += 1024)
        s += logf(g_density[i] + 1e-9f);
    red[t] = s;
    __syncthreads();
    #pragma unroll
    for (int o = 512; o; o >>= 1) {
        if (t < o) red[t] += red[t + o];
        __syncthreads();
    }
    if (t == 0) out[0] = -red[0] / (float)NROWS;
}

__global__ void dummy_kernel() {}   // launch-slot padding so ncu captures the GEMM

// ---------------- launch ----------------
extern "C" void kernel_launch(void* const* d_in, const int* in_sizes, int n_in,
                              void* d_out, int out_size) {
    (void)in_sizes; (void)n_in; (void)out_size;
    const float* x = (const float*)d_in[0];
    float* out = (float*)d_out;

    cudaFuncSetAttribute(kde_sym_kernel,
                         cudaFuncAttributeMaxDynamicSharedMemorySize, SMEM_BYTES);

    normalize_kernel<<<NROWS / 8, 256>>>(x);
    kde_sym_kernel<<<NCTA, 256, SMEM_BYTES>>>();
    entropy_kernel<<<1, 1024>>>(out);
    dummy_kernel<<<1, 32>>>();
    dummy_kernel<<<1, 32>>>();
}

// round 7
// speedup vs baseline: 1.7935x; 1.7935x over previous
#include <cuda_runtime.h>
#include <cuda_bf16.h>
#include <cstdint>

#define NROWS 16384
#define DIM   256
#define NT    128
#define NTILES 8256                // NT*(NT+1)/2
#define NCTA  148
#define NTHR  512
#define LDSB  272                  // bytes per smem row (256 + 16 pad)
#define KS    (5.0f / 256.0f)      // kappa folded with 16x16 quant scaling
#define TILE_SM_BYTES (128 * LDSB)             // 34816
#define SMEM_BYTES (3 * TILE_SM_BYTES)         // A + 2x B = 104448

__device__ uint8_t g_xq[NROWS * DIM];   // normalized rows, e4m3, scaled by 16
__device__ float   g_density[NROWS];

// ---------------- Phase 1: L2-normalize rows -> e4m3 (x16); zero g_density ----------------
static __device__ __forceinline__ uint16_t pack_e4m3x2(float lo, float hi) {
    uint16_t r;
    asm("cvt.rn.satfinite.e4m3x2.f32 %0, %1, %2;" : "=h"(r) : "f"(hi), "f"(lo));
    return r;
}

__global__ void normalize_kernel(const float* __restrict__ x) {
    int gwarp = (blockIdx.x * blockDim.x + threadIdx.x) >> 5;
    int lane  = threadIdx.x & 31;
    if (gwarp >= NROWS) return;
    const float4* p = reinterpret_cast<const float4*>(x + (size_t)gwarp * DIM);
    float4 v0 = p[lane * 2 + 0];
    float4 v1 = p[lane * 2 + 1];
    float ss = v0.x*v0.x + v0.y*v0.y + v0.z*v0.z + v0.w*v0.w
             + v1.x*v1.x + v1.y*v1.y + v1.z*v1.z + v1.w*v1.w;
    #pragma unroll
    for (int o = 16; o; o >>= 1) ss += __shfl_xor_sync(0xffffffffu, ss, o);
    float inv = 16.0f / fmaxf(sqrtf(ss), 1e-12f);

    uint16_t b01 = pack_e4m3x2(v0.x * inv, v0.y * inv);
    uint16_t b23 = pack_e4m3x2(v0.z * inv, v0.w * inv);
    uint16_t b45 = pack_e4m3x2(v1.x * inv, v1.y * inv);
    uint16_t b67 = pack_e4m3x2(v1.z * inv, v1.w * inv);
    uint2 out;
    out.x = (uint32_t)b01 | ((uint32_t)b23 << 16);
    out.y = (uint32_t)b45 | ((uint32_t)b67 << 16);
    reinterpret_cast<uint2*>(g_xq)[gwarp * (DIM / 8) + lane] = out;
    if (lane == 0) g_density[gwarp] = 0.0f;
}

// ---------------- helpers ----------------
static __device__ __forceinline__ void ldsm_x4(uint32_t* r, uint32_t addr) {
    asm volatile("ldmatrix.sync.aligned.m8n8.x4.shared.b16 {%0,%1,%2,%3}, [%4];\n"
                 : "=r"(r[0]), "=r"(r[1]), "=r"(r[2]), "=r"(r[3]) : "r"(addr));
}
static __device__ __forceinline__ void mma_fp8(float* c, const uint32_t* a, const uint32_t* b) {
    asm volatile("mma.sync.aligned.m16n8k32.row.col.f32.e4m3.e4m3.f32 "
                 "{%0,%1,%2,%3}, {%4,%5,%6,%7}, {%8,%9}, {%0,%1,%2,%3};\n"
                 : "+f"(c[0]), "+f"(c[1]), "+f"(c[2]), "+f"(c[3])
                 : "r"(a[0]), "r"(a[1]), "r"(a[2]), "r"(a[3]),
                   "r"(b[0]), "r"(b[1]));
}
#define CP_ASYNC16(dst, src) \
    asm volatile("cp.async.cg.shared.global [%0], [%1], 16;" :: "r"(dst), "l"(src) : "memory")
#define CP_COMMIT()  asm volatile("cp.async.commit_group;" ::: "memory")
#define CP_WAIT0()   asm volatile("cp.async.wait_group 0;" :: : "memory")

// load a 128x256B fp8 tile (2048 x 16B, 4 per thread @512)
static __device__ __forceinline__ void load_tile(uint32_t dst_base, int grow0, int tid) {
    #pragma unroll
    for (int i = 0; i < 4; ++i) {
        int id = i * NTHR + tid;
        int r = id >> 4, u = id & 15;
        uint32_t dst = dst_base + (uint32_t)(r * LDSB + u * 16);
        const char* src = (const char*)g_xq + (size_t)(grow0 + r) * DIM + u * 16;
        CP_ASYNC16(dst, src);
    }
}

// pair-ordered global tile index -> (ti, tj), ti <= tj
static __device__ __forceinline__ void tile_of(int q, int& ti, int& tj) {
    int p = q / 129, r = q - p * 129;
    int seg1 = NT - p;
    if (r < seg1) { ti = p;          tj = p + r; }
    else          { ti = NT - 1 - p; tj = NT - 1 - p + (r - seg1); }
}

// 4 exps of prev tile's accumulators, interleaved into mainloop (MUFU/FMA pipes)
static __device__ __forceinline__ void epi_chunk4(int ks, float cfrB[2][4][4],
                                                  float rowacc[2][2], float colaccP[4][2]) {
    int mf = ks & 1, nf = ks >> 1;
    float e0 = __expf(KS * cfrB[mf][nf][0]);
    float e1 = __expf(KS * cfrB[mf][nf][1]);
    float e2 = __expf(KS * cfrB[mf][nf][2]);
    float e3 = __expf(KS * cfrB[mf][nf][3]);
    rowacc[mf][0] += e0 + e1;
    rowacc[mf][1] += e2 + e3;
    if (mf == 0) { colaccP[nf][0]  = e0 + e2; colaccP[nf][1]  = e1 + e3; }
    else         { colaccP[nf][0] += e0 + e2; colaccP[nf][1] += e1 + e3; }
}

template <bool EPI>
static __device__ __forceinline__ void tile_mainloop(
    uint32_t Ab, uint32_t Bb, int a_rb, int b_rb,
    float cfrA[2][4][4], float cfrB[2][4][4],
    float rowacc[2][2], float colaccP[4][2])
{
    #pragma unroll
    for (int ks = 0; ks < 8; ++ks) {
        int k0 = ks * 32;
        uint32_t a[2][4];
        #pragma unroll
        for (int mf = 0; mf < 2; ++mf)
            ldsm_x4(a[mf], Ab + (uint32_t)(mf * 16 * LDSB + a_rb + k0));
        uint32_t bfr[4][2];
        #pragma unroll
        for (int pp = 0; pp < 2; ++pp) {
            uint32_t t[4];
            ldsm_x4(t, Bb + (uint32_t)(pp * 16 * LDSB + b_rb + k0));
            bfr[2*pp][0]   = t[0]; bfr[2*pp][1]   = t[1];
            bfr[2*pp+1][0] = t[2]; bfr[2*pp+1][1] = t[3];
        }
        #pragma unroll
        for (int mf = 0; mf < 2; ++mf)
            #pragma unroll
            for (int nf = 0; nf < 4; ++nf)
                mma_fp8(cfrA[mf][nf], a[mf], bfr[nf]);
        if (EPI)
            epi_chunk4(ks, cfrB, rowacc, colaccP);
    }
}

static __device__ __forceinline__ void flush_cols(float colaccP[4][2], int tj,
                                                  int warp_n, int lane) {
    #pragma unroll
    for (int nf = 0; nf < 4; ++nf)
        #pragma unroll
        for (int hh = 0; hh < 2; ++hh) {
            float s = colaccP[nf][hh];
            s += __shfl_xor_sync(0xffffffffu, s, 4);
            s += __shfl_xor_sync(0xffffffffu, s, 8);
            s += __shfl_xor_sync(0xffffffffu, s, 16);
            if (lane < 4)
                atomicAdd(&g_density[tj * 128 + warp_n * 32 + nf * 8 + 2 * lane + hh], s);
        }
}

static __device__ __forceinline__ void flush_rows(float rowacc[2][2], int ti,
                                                  int warp_m, int lane) {
    #pragma unroll
    for (int mf = 0; mf < 2; ++mf)
        #pragma unroll
        for (int rp = 0; rp < 2; ++rp) {
            float s = rowacc[mf][rp];
            s += __shfl_xor_sync(0xffffffffu, s, 1);
            s += __shfl_xor_sync(0xffffffffu, s, 2);
            if ((lane & 3) == 0)
                atomicAdd(&g_density[ti * 128 + warp_m * 32 + mf * 16 + rp * 8 + (lane >> 2)], s);
            rowacc[mf][rp] = 0.f;
        }
}

// ---------------- Phase 2: persistent FP8 symmetric GEMM, pipelined epilogue ----------------
__global__ void __launch_bounds__(NTHR, 1) kde_sym_kernel() {
    extern __shared__ uint8_t sm[];
    uint32_t A_sm = (uint32_t)__cvta_generic_to_shared(sm);
    uint32_t B_sm = A_sm + TILE_SM_BYTES;

    int tid  = threadIdx.x;
    int lane = tid & 31;
    int wid  = tid >> 5;
    int warp_m = wid & 3;        // 4 warps in M: 32 rows each
    int warp_n = wid >> 2;       // 4 warps in N: 32 cols each

    int qbeg = (int)(((long long)blockIdx.x * NTILES) / NCTA);
    int qend = (int)(((long long)(blockIdx.x + 1) * NTILES) / NCTA);

    int a_rb = (lane & 15) * LDSB + ((lane >> 4) * 16);
    int b_rb = ((lane & 7) + ((lane >> 4) << 3)) * LDSB + (((lane >> 3) & 1) * 16);
    uint32_t Ab = A_sm + (uint32_t)(warp_m * 32 * LDSB);

    int ti, tj;
    tile_of(qbeg, ti, tj);
    int cur_ti = ti;

    load_tile(A_sm, ti * 128, tid);
    load_tile(B_sm, tj * 128, tid);
    CP_COMMIT();
    CP_WAIT0();
    __syncthreads();

    float rowacc[2][2] = {{0.f,0.f},{0.f,0.f}};
    float cfrA[2][4][4], cfrB[2][4][4], colaccP[4][2];
    int cur = 0;
    int prev_tj = 0;
    bool prev_diag = false, have_prev = false;

    for (int q = qbeg; q < qend; ++q) {
        tile_of(q, ti, tj);
        if (q > qbeg) { CP_WAIT0(); __syncthreads(); }   // B(q) resident in buf cur

        int flush_ti = -1;
        if (ti != cur_ti) {                               // rare: <=2 per CTA
            load_tile(A_sm, ti * 128, tid);
            CP_COMMIT(); CP_WAIT0(); __syncthreads();
            flush_ti = cur_ti;
            cur_ti = ti;
        }

        if (q + 1 < qend) {                               // prefetch next B
            int nti, ntj;
            tile_of(q + 1, nti, ntj);
            load_tile(B_sm + (cur ^ 1) * TILE_SM_BYTES, ntj * 128, tid);
            CP_COMMIT();
        }

        #pragma unroll
        for (int mf = 0; mf < 2; ++mf)
            #pragma unroll
            for (int nf = 0; nf < 4; ++nf)
                #pragma unroll
                for (int e = 0; e < 4; ++e) cfrA[mf][nf][e] = 0.f;

        uint32_t Bb = B_sm + (uint32_t)(cur * TILE_SM_BYTES + warp_n * 32 * LDSB);
        if (have_prev)
            tile_mainloop<true >(Ab, Bb, a_rb, b_rb, cfrA, cfrB, rowacc, colaccP);
        else
            tile_mainloop<false>(Ab, Bb, a_rb, b_rb, cfrA, cfrB, rowacc, colaccP);

        if (have_prev && !prev_diag) flush_cols(colaccP, prev_tj, warp_n, lane);
        if (flush_ti >= 0) flush_rows(rowacc, flush_ti, warp_m, lane);

        #pragma unroll
        for (int mf = 0; mf < 2; ++mf)
            #pragma unroll
            for (int nf = 0; nf < 4; ++nf)
                #pragma unroll
                for (int e = 0; e < 4; ++e) cfrB[mf][nf][e] = cfrA[mf][nf][e];

        prev_tj = tj;
        prev_diag = (ti == tj);
        have_prev = true;
        cur ^= 1;
    }

    // drain last tile's epilogue
    #pragma unroll
    for (int ks = 0; ks < 8; ++ks)
        epi_chunk4(ks, cfrB, rowacc, colaccP);
    if (!prev_diag) flush_cols(colaccP, prev_tj, warp_n, lane);
    flush_rows(rowacc, cur_ti, warp_m, lane);
}

// ---------------- Phase 3: entropy = -mean(log(density + 1e-9)) ----------------
__global__ void entropy_kernel(float* __restrict__ out) {
    __shared__ float red[1024];
    int t = threadIdx.x;
    float s = 0.f;
    for (int i = t; i < NROWS; i += 1024)
        s += logf(g_density[i] + 1e-9f);
    red[t] = s;
    __syncthreads();
    #pragma unroll
    for (int o = 512; o; o >>= 1) {
        if (t < o) red[t] += red[t + o];
        __syncthreads();
    }
    if (t == 0) out[0] = -red[0] / (float)NROWS;
}

__global__ void dummy_kernel() {}   // padding: puts GEMM in ncu's capture slot (pos 3)

// ---------------- launch ----------------
extern "C" void kernel_launch(void* const* d_in, const int* in_sizes, int n_in,
                              void* d_out, int out_size) {
    (void)in_sizes; (void)n_in; (void)out_size;
    const float* x = (const float*)d_in[0];
    float* out = (float*)d_out;

    cudaFuncSetAttribute(kde_sym_kernel,
                         cudaFuncAttributeMaxDynamicSharedMemorySize, SMEM_BYTES);

    normalize_kernel<<<NROWS / 8, 256>>>(x);   // pos 0
    dummy_kernel<<<1, 32>>>();                 // pos 1
    dummy_kernel<<<1, 32>>>();                 // pos 2
    kde_sym_kernel<<<NCTA, NTHR, SMEM_BYTES>>>();  // pos 3 <- ncu capture slot
    entropy_kernel<<<1, 1024>>>(out);          // pos 4
}